// round 2
// baseline (speedup 1.0000x reference)
#include <cuda_runtime.h>
#include <cstdint>

// ---------------------------------------------------------------------------
// LIF layer forward:
//   cur = x @ W^T + bias                      (GEMM, M=B*T, N=OUT, K=IN)
//   scan over t:  v = d*v*(1-z) + (1-d)*(cur_t + z @ R^T);  z = v>=1
//   outputs = z_seq [B,T,OUT]
//   states  = stack([v_full, z_full])  [2, B, T+1, OUT]
// d_out = [outputs | states] flattened in return order.
// ---------------------------------------------------------------------------

#define IN_DIM  512
#define OUT_DIM 512

// Scratch for R^T (recurrent transposed): static device global (no alloc).
__device__ float g_RT[OUT_DIM * OUT_DIM];

// ---------------- transpose R -> RT (RT[j][o] = R[o][j]) -------------------
__global__ void transpose512_kernel(const float* __restrict__ R) {
    __shared__ float tile[32][33];
    int x = blockIdx.x * 32 + threadIdx.x;
    int y = blockIdx.y * 32 + threadIdx.y;
    tile[threadIdx.y][threadIdx.x] = R[y * OUT_DIM + x];
    __syncthreads();
    int xo = blockIdx.y * 32 + threadIdx.x;
    int yo = blockIdx.x * 32 + threadIdx.y;
    g_RT[yo * OUT_DIM + xo] = tile[threadIdx.x][threadIdx.y];
}

// ---------------- GEMM: C[m][n] = sum_k A[m][k] * Wm[n][k] + bias[n] -------
// BM=128, BN=128, BK=8, 256 threads, 8x8 per thread.
__global__ __launch_bounds__(256, 2)
void gemm_kernel(const float* __restrict__ A,
                 const float* __restrict__ Wm,
                 const float* __restrict__ bias,
                 float* __restrict__ C) {
    const int K = IN_DIM;
    const int N = OUT_DIM;
    __shared__ float As[8][128];
    __shared__ float Bs[8][128];

    int tid = threadIdx.x;
    int m0 = blockIdx.x * 128;
    int n0 = blockIdx.y * 128;

    int lr = tid >> 1;          // 0..127
    int lc = (tid & 1) * 4;     // 0 or 4
    int tx = tid & 15;
    int ty = tid >> 4;

    const float* Aload = A + (size_t)(m0 + lr) * K + lc;
    const float* Bload = Wm + (size_t)(n0 + lr) * K + lc;

    float acc[8][8];
#pragma unroll
    for (int i = 0; i < 8; i++)
#pragma unroll
        for (int j = 0; j < 8; j++) acc[i][j] = 0.f;

    for (int k0 = 0; k0 < K; k0 += 8) {
        float4 a4 = *(const float4*)(Aload + k0);
        float4 b4 = *(const float4*)(Bload + k0);
        As[lc + 0][lr] = a4.x; As[lc + 1][lr] = a4.y;
        As[lc + 2][lr] = a4.z; As[lc + 3][lr] = a4.w;
        Bs[lc + 0][lr] = b4.x; Bs[lc + 1][lr] = b4.y;
        Bs[lc + 2][lr] = b4.z; Bs[lc + 3][lr] = b4.w;
        __syncthreads();

#pragma unroll
        for (int kk = 0; kk < 8; kk++) {
            float ar[8], br[8];
#pragma unroll
            for (int i = 0; i < 4; i++) {
                ar[i]     = As[kk][ty * 8 + i];
                ar[i + 4] = As[kk][ty * 8 + 4 + i];
                br[i]     = Bs[kk][tx * 8 + i];
                br[i + 4] = Bs[kk][tx * 8 + 4 + i];
            }
#pragma unroll
            for (int i = 0; i < 8; i++)
#pragma unroll
                for (int j = 0; j < 8; j++)
                    acc[i][j] = fmaf(ar[i], br[j], acc[i][j]);
        }
        __syncthreads();
    }

#pragma unroll
    for (int i = 0; i < 8; i++) {
        size_t mrow = (size_t)(m0 + ty * 8 + i) * N;
#pragma unroll
        for (int j = 0; j < 8; j += 4) {
            int n = n0 + tx * 8 + j;
            float4 o;
            o.x = acc[i][j + 0] + bias[n + 0];
            o.y = acc[i][j + 1] + bias[n + 1];
            o.z = acc[i][j + 2] + bias[n + 2];
            o.w = acc[i][j + 3] + bias[n + 3];
            *(float4*)(C + mrow + n) = o;
        }
    }
}

// ---------------- Sequential LIF scan: one CTA per batch element ------------
// 512 threads; thread o owns neuron o of batch b = blockIdx.x.
__global__ __launch_bounds__(OUT_DIM, 1)
void scan_kernel(const float* __restrict__ cur,
                 const float* __restrict__ decay,
                 float* __restrict__ outputs,
                 float* __restrict__ statesV,
                 float* __restrict__ statesZ,
                 int T) {
    int b = blockIdx.x;
    int o = threadIdx.x;
    int wid = o >> 5;
    int lane = o & 31;

    __shared__ unsigned smask[OUT_DIM / 32];  // spike bitmask of previous step
    if (o < OUT_DIM / 32) smask[o] = 0u;

    const float d   = decay[o];
    const float omd = 1.f - d;

    const float* curB = cur + (size_t)b * T * OUT_DIM;
    float* outB = outputs + (size_t)b * T * OUT_DIM;
    float* svB  = statesV + (size_t)b * (T + 1) * OUT_DIM;
    float* szB  = statesZ + (size_t)b * (T + 1) * OUT_DIM;

    // t = 0 initial state slices
    svB[o] = 0.f;
    szB[o] = 0.f;

    float v = 0.f;
    float z = 0.f;
    int anySpike = 0;

    __syncthreads();  // smask init visible

    float c = curB[o];  // prefetch t=0
    for (int t = 0; t < T; t++) {
        // prefetch next timestep's current (hides DRAM latency behind the step)
        float c_next = 0.f;
        if (t + 1 < T) c_next = curB[(size_t)(t + 1) * OUT_DIM + o];

        float soma = c;
        if (anySpike) {
            // gather recurrent contributions from previous-step spikes
#pragma unroll 1
            for (int w = 0; w < OUT_DIM / 32; w++) {
                unsigned m = smask[w];
                while (m) {
                    int j = w * 32 + (__ffs(m) - 1);
                    m &= (m - 1);
                    soma += g_RT[j * OUT_DIM + o];
                }
            }
        }

        v = d * (v * (1.f - z)) + omd * soma;
        z = (v - 1.f >= 0.f) ? 1.f : 0.f;

        size_t idx  = (size_t)t * OUT_DIM + o;
        size_t idx1 = (size_t)(t + 1) * OUT_DIM + o;
        outB[idx]  = z;
        svB[idx1]  = v;
        szB[idx1]  = z;

        unsigned bal = __ballot_sync(0xffffffffu, z > 0.f);
        // full barrier + block-wide spike count; separates smask reads (above)
        // from smask writes (below)
        anySpike = __syncthreads_count(z > 0.f);
        if (anySpike) {
            if (lane == 0) smask[wid] = bal;
            __syncthreads();  // uniform branch: anySpike is block-uniform
        }

        c = c_next;
    }
}

// ---------------------------------------------------------------------------
extern "C" void kernel_launch(void* const* d_in, const int* in_sizes, int n_in,
                              void* d_out, int out_size) {
    const float* x      = (const float*)d_in[0];  // [B, T, IN]
    const float* weight = (const float*)d_in[1];  // [OUT, IN]
    const float* bias   = (const float*)d_in[2];  // [OUT]
    const float* recur  = (const float*)d_in[3];  // [OUT, OUT]
    const float* decay  = (const float*)d_in[4];  // [OUT]

    const int OUT = in_sizes[2];                  // 512
    const int IN  = in_sizes[1] / OUT;            // 512
    const long long M = (long long)in_sizes[0] / IN;   // B*T
    // out_size = OUT*(3*B*T + 2*B)  =>  B = (out_size/OUT - 3*M)/2
    const long long B = (((long long)out_size / OUT) - 3 * M) / 2;
    const int T = (int)(M / B);

    float* outputs = (float*)d_out;                               // [B,T,OUT]
    float* statesV = outputs + (size_t)B * T * OUT;               // [B,T+1,OUT]
    float* statesZ = statesV + (size_t)B * (T + 1) * OUT;         // [B,T+1,OUT]

    // scratch cur buffer: reuse statesV region? No — scan reads cur while
    // writing statesV. Use statesZ? Also written during scan. Instead place
    // cur in a dedicated static buffer region: we stash it in d_out's outputs
    // region? outputs is written per-step AFTER cur[t] is consumed at step t,
    // but cur[b,t',:] for t'>t must survive — outputs[b,t,:] written at step t
    // only after cur[b,t,:] read, and outputs/cur indices align (same [B,T,OUT]
    // layout). Writing outputs[idx] happens strictly after reading cur[idx],
    // and no later step re-reads cur[idx]. So cur can ALIAS outputs safely.
    float* cur = outputs;

    // 1) RT = R^T
    {
        dim3 grid(OUT / 32, OUT / 32), block(32, 32);
        transpose512_kernel<<<grid, block>>>(recur);
    }
    // 2) cur = x @ W^T + bias
    {
        dim3 grid((unsigned)(M / 128), OUT / 128);
        gemm_kernel<<<grid, 256>>>(x, weight, bias, cur);
    }
    // 3) sequential scan
    {
        scan_kernel<<<(unsigned)B, OUT>>>(cur, decay, outputs, statesV, statesZ, T);
    }
}

// round 4
// speedup vs baseline: 2.2052x; 2.2052x over previous
#include <cuda_runtime.h>
#include <cuda_bf16.h>
#include <cstdint>

// ---------------------------------------------------------------------------
// LIF layer forward (sm_103 base ISA — no tcgen05 available at compile target):
//   cur = x @ W^T + bias   (3-pass split-bf16 HMMA GEMM: ~fp32 precision)
//   scan: v = d*v*(1-z) + (1-d)*(cur_t + z @ R^T);  z = (v >= 1)
// d_out = [outputs | statesV | statesZ]
// ---------------------------------------------------------------------------

#define IN_DIM  512
#define OUT_DIM 512
#define MAX_M   64000

// Static device scratch (allocation-free contract).
__device__ __nv_bfloat16 g_xhi[(size_t)MAX_M * IN_DIM];
__device__ __nv_bfloat16 g_xlo[(size_t)MAX_M * IN_DIM];
__device__ __nv_bfloat16 g_whi[(size_t)OUT_DIM * IN_DIM];
__device__ __nv_bfloat16 g_wlo[(size_t)OUT_DIM * IN_DIM];
__device__ float         g_RT [(size_t)OUT_DIM * OUT_DIM];

// ======================= conversion kernels =================================
__global__ void convert_x_kernel(const float* __restrict__ x, long long n4) {
    long long i = (long long)blockIdx.x * blockDim.x + threadIdx.x;
    if (i >= n4) return;
    float4 v = ((const float4*)x)[i];
    float vv[4] = {v.x, v.y, v.z, v.w};
    __nv_bfloat16 h[4], l[4];
#pragma unroll
    for (int k = 0; k < 4; k++) {
        h[k] = __float2bfloat16_rn(vv[k]);
        l[k] = __float2bfloat16_rn(vv[k] - __bfloat162float(h[k]));
    }
    __nv_bfloat162* hi2 = (__nv_bfloat162*)g_xhi;
    __nv_bfloat162* lo2 = (__nv_bfloat162*)g_xlo;
    hi2[i * 2]     = __halves2bfloat162(h[0], h[1]);
    hi2[i * 2 + 1] = __halves2bfloat162(h[2], h[3]);
    lo2[i * 2]     = __halves2bfloat162(l[0], l[1]);
    lo2[i * 2 + 1] = __halves2bfloat162(l[2], l[3]);
}

__global__ void convert_w_kernel(const float* __restrict__ w) {
    int i = blockIdx.x * blockDim.x + threadIdx.x;  // 65536 float4 chunks
    float4 v = ((const float4*)w)[i];
    float vv[4] = {v.x, v.y, v.z, v.w};
    __nv_bfloat16 h[4], l[4];
#pragma unroll
    for (int k = 0; k < 4; k++) {
        h[k] = __float2bfloat16_rn(vv[k]);
        l[k] = __float2bfloat16_rn(vv[k] - __bfloat162float(h[k]));
    }
    __nv_bfloat162* hi2 = (__nv_bfloat162*)g_whi;
    __nv_bfloat162* lo2 = (__nv_bfloat162*)g_wlo;
    hi2[i * 2]     = __halves2bfloat162(h[0], h[1]);
    hi2[i * 2 + 1] = __halves2bfloat162(h[2], h[3]);
    lo2[i * 2]     = __halves2bfloat162(l[0], l[1]);
    lo2[i * 2 + 1] = __halves2bfloat162(l[2], l[3]);
}

__global__ void transpose512_kernel(const float* __restrict__ R) {
    __shared__ float tile[32][33];
    int x = blockIdx.x * 32 + threadIdx.x;
    int y = blockIdx.y * 32 + threadIdx.y;
    tile[threadIdx.y][threadIdx.x] = R[y * OUT_DIM + x];
    __syncthreads();
    int xo = blockIdx.y * 32 + threadIdx.x;
    int yo = blockIdx.x * 32 + threadIdx.y;
    g_RT[yo * OUT_DIM + xo] = tile[threadIdx.x][threadIdx.y];
}

// ======================= HMMA GEMM ==========================================
// C[m][n] = sum_k x[m][k]*W[n][k] + bias[n]
// CTA 128x128, BK=64 (8 stages), double-buffered cp.async.
// Warp grid 4(m) x 2(n); warp tile 32x64; mma.sync m16n8k16 bf16.
//
// SMEM stage layout (stride 72 bf16 = 144B rows; conflict-free frag loads):
//   Ah[128][72] Al[128][72] Bh[128][72] Bl[128][72]   (18432 B each)
#define TSTRIDE   72                 // bf16 elements per SMEM row
#define PART_B    (128 * TSTRIDE * 2)          // 18432
#define STAGE_B   (4 * PART_B)                 // 73728
#define SMEM_GEMM (2 * STAGE_B)                // 147456

__device__ __forceinline__ void cp16(void* dst, const void* src) {
    uint32_t d;
    asm("{ .reg .u64 t; cvta.to.shared.u64 t, %1; cvt.u32.u64 %0, t; }"
        : "=r"(d) : "l"(dst));
    asm volatile("cp.async.cg.shared.global [%0], [%1], 16;" :: "r"(d), "l"(src));
}

__device__ __forceinline__ void mma_bf16(float* d, const uint32_t* a,
                                         const uint32_t* b) {
    asm volatile(
        "mma.sync.aligned.m16n8k16.row.col.f32.bf16.bf16.f32 "
        "{%0,%1,%2,%3}, {%4,%5,%6,%7}, {%8,%9}, {%0,%1,%2,%3};"
        : "+f"(d[0]), "+f"(d[1]), "+f"(d[2]), "+f"(d[3])
        : "r"(a[0]), "r"(a[1]), "r"(a[2]), "r"(a[3]), "r"(b[0]), "r"(b[1]));
}

__device__ __forceinline__ void load_stage(char* sm, int buf,
        const __nv_bfloat16* Ah, const __nv_bfloat16* Al,
        const __nv_bfloat16* Bh, const __nv_bfloat16* Bl,
        int k0, int tid) {
    char* base = sm + buf * STAGE_B;
    const __nv_bfloat16* srcs[4] = {Ah, Al, Bh, Bl};
#pragma unroll
    for (int p = 0; p < 4; p++) {
        char* pb = base + p * PART_B;
        const __nv_bfloat16* gp = srcs[p] + k0;
#pragma unroll
        for (int it = 0; it < 4; it++) {
            int chunk = it * 256 + tid;     // 1024 chunks: 128 rows x 8x16B
            int row = chunk >> 3;
            int cc  = chunk & 7;
            cp16(pb + row * (TSTRIDE * 2) + cc * 16,
                 gp + (size_t)row * IN_DIM + cc * 8);
        }
    }
    asm volatile("cp.async.commit_group;");
}

__global__ __launch_bounds__(256)
void gemm_hmma_kernel(const float* __restrict__ bias, float* __restrict__ C) {
    extern __shared__ char sm[];
    const int tid  = threadIdx.x;
    const int wid  = tid >> 5;
    const int lane = tid & 31;
    const int g = lane >> 2, t = lane & 3;
    const int wm = wid >> 1;          // 0..3 -> m offset wm*32
    const int wn = wid & 1;           // 0..1 -> n offset wn*64
    const int m0 = blockIdx.x * 128;
    const int n0 = blockIdx.y * 128;

    const __nv_bfloat16* Ah = g_xhi + (size_t)m0 * IN_DIM;
    const __nv_bfloat16* Al = g_xlo + (size_t)m0 * IN_DIM;
    const __nv_bfloat16* Bh = g_whi + (size_t)n0 * IN_DIM;
    const __nv_bfloat16* Bl = g_wlo + (size_t)n0 * IN_DIM;

    float d[2][8][4];
#pragma unroll
    for (int mi = 0; mi < 2; mi++)
#pragma unroll
        for (int nj = 0; nj < 8; nj++)
#pragma unroll
            for (int r = 0; r < 4; r++) d[mi][nj][r] = 0.f;

    load_stage(sm, 0, Ah, Al, Bh, Bl, 0, tid);

#pragma unroll 1
    for (int s = 0; s < 8; s++) {
        if (s < 7) {
            load_stage(sm, (s + 1) & 1, Ah, Al, Bh, Bl, (s + 1) * 64, tid);
            asm volatile("cp.async.wait_group 1;");
        } else {
            asm volatile("cp.async.wait_group 0;");
        }
        __syncthreads();

        const uint32_t* As = (const uint32_t*)(sm + (s & 1) * STAGE_B);
        const uint32_t* Als = As + PART_B / 4;
        const uint32_t* Bs  = As + 2 * (PART_B / 4);
        const uint32_t* Bls = As + 3 * (PART_B / 4);
        const int HS = TSTRIDE / 2;   // 36 b32 per row

#pragma unroll
        for (int kk = 0; kk < 4; kk++) {
            uint32_t ah[2][4], al[2][4];
#pragma unroll
            for (int mi = 0; mi < 2; mi++) {
                int r0 = wm * 32 + mi * 16 + g;
                int cb = kk * 8 + t;
                ah[mi][0] = As [r0 * HS + cb];
                ah[mi][1] = As [(r0 + 8) * HS + cb];
                ah[mi][2] = As [r0 * HS + cb + 4];
                ah[mi][3] = As [(r0 + 8) * HS + cb + 4];
                al[mi][0] = Als[r0 * HS + cb];
                al[mi][1] = Als[(r0 + 8) * HS + cb];
                al[mi][2] = Als[r0 * HS + cb + 4];
                al[mi][3] = Als[(r0 + 8) * HS + cb + 4];
            }
            uint32_t bh[8][2], bl[8][2];
#pragma unroll
            for (int nj = 0; nj < 8; nj++) {
                int rn = wn * 64 + nj * 8 + g;
                int cb = kk * 8 + t;
                bh[nj][0] = Bs [rn * HS + cb];
                bh[nj][1] = Bs [rn * HS + cb + 4];
                bl[nj][0] = Bls[rn * HS + cb];
                bl[nj][1] = Bls[rn * HS + cb + 4];
            }
#pragma unroll
            for (int mi = 0; mi < 2; mi++)
#pragma unroll
                for (int nj = 0; nj < 8; nj++) {
                    mma_bf16(d[mi][nj], ah[mi], bh[nj]);
                    mma_bf16(d[mi][nj], ah[mi], bl[nj]);
                    mma_bf16(d[mi][nj], al[mi], bh[nj]);
                }
        }
        __syncthreads();
    }

    // Epilogue: direct float2 stores + bias
#pragma unroll
    for (int nj = 0; nj < 8; nj++) {
        int cc = n0 + wn * 64 + nj * 8 + 2 * t;
        float2 bv = *(const float2*)&bias[cc];
#pragma unroll
        for (int mi = 0; mi < 2; mi++) {
            int r0 = m0 + wm * 32 + mi * 16 + g;
            float2 o0 = {d[mi][nj][0] + bv.x, d[mi][nj][1] + bv.y};
            float2 o1 = {d[mi][nj][2] + bv.x, d[mi][nj][3] + bv.y};
            *(float2*)&C[(size_t)r0 * OUT_DIM + cc]       = o0;
            *(float2*)&C[(size_t)(r0 + 8) * OUT_DIM + cc] = o1;
        }
    }
}

// ======================= LIF sequential scan ================================
__device__ __forceinline__ void lif_step(
    float c, float& v, float& z, int& anySpike,
    unsigned* smask, int o, int wid, int lane,
    float d, float omd,
    float* __restrict__ outB, float* __restrict__ svB, float* __restrict__ szB,
    int t)
{
    float soma = c;
    if (anySpike) {
#pragma unroll 1
        for (int w = 0; w < OUT_DIM / 32; w++) {
            unsigned m = smask[w];
            while (m) {
                int j = w * 32 + (__ffs(m) - 1);
                m &= (m - 1);
                soma += g_RT[(size_t)j * OUT_DIM + o];
            }
        }
    }
    v = d * (v * (1.f - z)) + omd * soma;
    z = (v >= 1.f) ? 1.f : 0.f;
    outB[(size_t)t * OUT_DIM + o]      = z;
    svB[(size_t)(t + 1) * OUT_DIM + o] = v;
    szB[(size_t)(t + 1) * OUT_DIM + o] = z;
    unsigned bal = __ballot_sync(0xffffffffu, z > 0.f);
    anySpike = __syncthreads_count(z > 0.f);   // barrier: reads above / writes below
    if (anySpike) {
        if (lane == 0) smask[wid] = bal;
        __syncthreads();                       // anySpike is block-uniform
    }
}

__global__ __launch_bounds__(OUT_DIM, 1)
void scan_kernel(const float* __restrict__ cur,
                 const float* __restrict__ decay,
                 float* __restrict__ outputs,
                 float* __restrict__ statesV,
                 float* __restrict__ statesZ,
                 int T) {
    int b = blockIdx.x;
    int o = threadIdx.x;
    int wid = o >> 5, lane = o & 31;

    __shared__ unsigned smask[OUT_DIM / 32];
    if (o < OUT_DIM / 32) smask[o] = 0u;

    const float d   = decay[o];
    const float omd = 1.f - d;

    const float* curB = cur + (size_t)b * T * OUT_DIM;
    float* outB = outputs + (size_t)b * T * OUT_DIM;
    float* svB  = statesV + (size_t)b * (T + 1) * OUT_DIM;
    float* szB  = statesZ + (size_t)b * (T + 1) * OUT_DIM;

    svB[o] = 0.f;
    szB[o] = 0.f;

    float v = 0.f, z = 0.f;
    int anySpike = 0;
    __syncthreads();

    // 4-deep prefetch ring hides DRAM latency (MLP=4) across the barrier chain
    float c0 = 0.f, c1 = 0.f, c2 = 0.f, c3 = 0.f;
    if (T > 0) c0 = curB[o];
    if (T > 1) c1 = curB[(size_t)OUT_DIM + o];
    if (T > 2) c2 = curB[(size_t)2 * OUT_DIM + o];
    if (T > 3) c3 = curB[(size_t)3 * OUT_DIM + o];

    int t = 0;
#pragma unroll 1
    for (; t + 3 < T; t += 4) {
        float n0 = (t + 4 < T) ? curB[(size_t)(t + 4) * OUT_DIM + o] : 0.f;
        lif_step(c0, v, z, anySpike, smask, o, wid, lane, d, omd, outB, svB, szB, t);
        float n1 = (t + 5 < T) ? curB[(size_t)(t + 5) * OUT_DIM + o] : 0.f;
        lif_step(c1, v, z, anySpike, smask, o, wid, lane, d, omd, outB, svB, szB, t + 1);
        float n2 = (t + 6 < T) ? curB[(size_t)(t + 6) * OUT_DIM + o] : 0.f;
        lif_step(c2, v, z, anySpike, smask, o, wid, lane, d, omd, outB, svB, szB, t + 2);
        float n3 = (t + 7 < T) ? curB[(size_t)(t + 7) * OUT_DIM + o] : 0.f;
        lif_step(c3, v, z, anySpike, smask, o, wid, lane, d, omd, outB, svB, szB, t + 3);
        c0 = n0; c1 = n1; c2 = n2; c3 = n3;
    }
    if (t < T) { lif_step(c0, v, z, anySpike, smask, o, wid, lane, d, omd, outB, svB, szB, t); t++; }
    if (t < T) { lif_step(c1, v, z, anySpike, smask, o, wid, lane, d, omd, outB, svB, szB, t); t++; }
    if (t < T) { lif_step(c2, v, z, anySpike, smask, o, wid, lane, d, omd, outB, svB, szB, t); t++; }
}

// ---------------------------------------------------------------------------
extern "C" void kernel_launch(void* const* d_in, const int* in_sizes, int n_in,
                              void* d_out, int out_size) {
    const float* x      = (const float*)d_in[0];  // [B, T, IN]
    const float* weight = (const float*)d_in[1];  // [OUT, IN]
    const float* bias   = (const float*)d_in[2];  // [OUT]
    const float* recur  = (const float*)d_in[3];  // [OUT, OUT]
    const float* decay  = (const float*)d_in[4];  // [OUT]

    const int OUT = in_sizes[2];                         // 512
    const int IN  = in_sizes[1] / OUT;                   // 512
    const long long M = (long long)in_sizes[0] / IN;     // B*T
    const long long B = (((long long)out_size / OUT) - 3 * M) / 2;
    const int T = (int)(M / B);

    float* outputs = (float*)d_out;                        // [B,T,OUT]
    float* statesV = outputs + (size_t)B * T * OUT;        // [B,T+1,OUT]
    float* statesZ = statesV + (size_t)B * (T + 1) * OUT;  // [B,T+1,OUT]
    // cur aliases outputs: cur[b,t,o] is read (<=4 steps early) strictly before
    // outputs[b,t,o] is written by the same thread; indices coincide 1:1.
    float* cur = outputs;

    // 1) fp32 -> bf16 hi/lo splits
    long long n4x = M * IN / 4;
    convert_x_kernel<<<(unsigned)((n4x + 255) / 256), 256>>>(x, n4x);
    convert_w_kernel<<<(OUT * IN / 4) / 256, 256>>>(weight);

    // 2) R^T
    {
        dim3 grid(OUT / 32, OUT / 32), block(32, 32);
        transpose512_kernel<<<grid, block>>>(recur);
    }

    // 3) HMMA split-bf16 GEMM: cur = x @ W^T + bias
    cudaFuncSetAttribute(gemm_hmma_kernel,
                         cudaFuncAttributeMaxDynamicSharedMemorySize, SMEM_GEMM);
    {
        dim3 grid((unsigned)(M / 128), OUT / 128);
        gemm_hmma_kernel<<<grid, 256, SMEM_GEMM>>>(bias, cur);
    }

    // 4) sequential LIF scan
    scan_kernel<<<(unsigned)B, OUT>>>(cur, decay, outputs, statesV, statesZ, T);
}